// round 8
// baseline (speedup 1.0000x reference)
#include <cuda_runtime.h>
#include <cuda_bf16.h>
#include <math.h>

#define G_   512
#define NPG  90
#define NN   (G_ * NPG)      // 46080
#define DEG  20
#define EE   (NN * DEG)      // 921600
#define F_IN 90
#define HH   64
#define KK   70
#define PDIM (KK * HH)       // 4480
#define EB   2304            // per-graph edge bucket capacity (mean 1800, sd ~42)

// ---------------- device scratch (static, no allocations) ----------------
__device__ float g_t[NN * HH];      // X @ Wl  (message features)
__device__ float g_self[NN * HH];   // X @ Wr + b (self features)
__device__ float g_p[G_ * PDIM];    // pooled features
__device__ int   g_gcnt[G_];        // edges per graph
__device__ int   g_ebuck[G_ * EB];  // packed edges per graph: (dst_local<<7)|src_local

// ---------------- edge bucketing ----------------
__global__ void zero512() {
    g_gcnt[threadIdx.x] = 0;
}

__global__ void bucket_kernel(const int* __restrict__ src,
                              const int* __restrict__ dst) {
    int e = blockIdx.x * blockDim.x + threadIdx.x;
    if (e < EE) {
        int d = dst[e];
        int s = src[e];
        if ((unsigned)d < NN && (unsigned)s < NN) {
            int g = d / NPG;
            int dl = d - g * NPG;
            int sl = s - g * NPG;
            if ((unsigned)sl < NPG) {
                int slot = atomicAdd(&g_gcnt[g], 1);
                if (slot < EB)
                    g_ebuck[g * EB + slot] = (dl << 7) | sl;
            }
        }
    }
}

// ---------------- in-block counting sort helper ----------------
// pe[] holds 'edges' packed values; deg/offs/cur are [96] smem ints;
// es receives src_local bytes ordered by dst_local. 256 threads.
__device__ __forceinline__ void csort_edges(const int* pe, int edges,
                                            int* deg, int* offs, int* cur,
                                            unsigned char* es, int t) {
    if (t < 96) deg[t] = 0;
    __syncthreads();
    for (int i = t; i < edges; i += 256)
        atomicAdd(&deg[pe[i] >> 7], 1);
    __syncthreads();
    if (t < 32) {
        int l = t;
        int a0 = deg[3 * l], a1 = deg[3 * l + 1], a2 = deg[3 * l + 2];
        int s = a0 + a1 + a2;
        int sc = s;
        #pragma unroll
        for (int d = 1; d < 32; d <<= 1) {
            int v = __shfl_up_sync(0xFFFFFFFFu, sc, d);
            if (l >= d) sc += v;
        }
        int base = sc - s;
        offs[3 * l] = base;
        offs[3 * l + 1] = base + a0;
        offs[3 * l + 2] = base + a0 + a1;
        cur[3 * l] = base;
        cur[3 * l + 1] = base + a0;
        cur[3 * l + 2] = base + a0 + a1;
    }
    __syncthreads();
    for (int i = t; i < edges; i += 256) {
        int p = pe[i];
        int d = p >> 7;
        int pos = atomicAdd(&cur[d], 1);
        es[pos] = (unsigned char)(p & 127);
    }
    __syncthreads();
}

// ---------------- fused dual GEMM: T = X@Wl ; S = X@Wr + b ----------------
// blockDim 256; 128 rows per block (4 passes of 32 rows, 4 rowgroups x 8 rows)
template <int K, bool RELU>
__global__ void gemm_dual(const float* __restrict__ X,
                          const float* __restrict__ Wl,
                          const float* __restrict__ Wr,
                          const float* __restrict__ bias) {
    extern __shared__ float smem[];
    float* Ws = smem;               // [K][128]
    float* Xs = smem + K * 128;     // [32][K]

    int t = threadIdx.x;
    int c = t & 63;
    int rg = t >> 6;                // 0..3

    for (int idx = t; idx < K * 128; idx += 256) {
        int k = idx >> 7, cc = idx & 127;
        Ws[idx] = (cc < 64) ? Wl[k * 64 + cc] : Wr[k * 64 + (cc - 64)];
    }
    __syncthreads();

    int rowBase = blockIdx.x * 128;
    float bv = bias[c];

    for (int p = 0; p < 4; p++) {
        int r0 = rowBase + p * 32;
        for (int idx = t; idx < 32 * K; idx += 256) {
            int row = idx / K, k = idx - row * K;
            float v = X[(r0 + row) * K + k];
            Xs[row * K + k] = RELU ? fmaxf(v, 0.f) : v;
        }
        __syncthreads();

        float acc0[8], acc1[8];
        #pragma unroll
        for (int i = 0; i < 8; i++) { acc0[i] = 0.f; acc1[i] = 0.f; }

        const float* xb = Xs + (rg * 8) * K;
        #pragma unroll 2
        for (int k = 0; k < K; k++) {
            float w0 = Ws[k * 128 + c];
            float w1 = Ws[k * 128 + 64 + c];
            #pragma unroll
            for (int i = 0; i < 8; i++) {
                float xv = xb[i * K + k];
                acc0[i] = fmaf(xv, w0, acc0[i]);
                acc1[i] = fmaf(xv, w1, acc1[i]);
            }
        }
        #pragma unroll
        for (int i = 0; i < 8; i++) {
            int row = r0 + rg * 8 + i;
            g_t[row * 64 + c]    = acc0[i];
            g_self[row * 64 + c] = acc1[i] + bv;
        }
        __syncthreads();
    }
}

// ---------------- aggregation 1: h1 = mean_csr(t) + self -> x_train ----------------
// dyn smem: ts [NPG*64] floats | pe [EB] ints | es [EB] bytes
__global__ void aggregate1(float* __restrict__ out_h) {
    extern __shared__ float dyn[];
    float* ts = dyn;                               // 23040 B
    int*   pe = (int*)(dyn + NPG * HH);            // 9216 B
    unsigned char* es = (unsigned char*)(pe + EB); // 2304 B
    __shared__ int deg[96], offs[96], cur[96];

    int g = blockIdx.x;
    int base = g * NPG;
    int t = threadIdx.x;

    for (int i = t; i < NPG * HH; i += 256)
        ts[i] = g_t[base * HH + i];
    int edges = min(g_gcnt[g], EB);
    for (int i = t; i < edges; i += 256)
        pe[i] = g_ebuck[g * EB + i];
    __syncthreads();

    csort_edges(pe, edges, deg, offs, cur, es, t);

    int wid = t >> 5, lane = t & 31;
    for (int n = wid; n < NPG; n += 8) {
        int node = base + n;
        int s0 = offs[n], cnt = deg[n];
        float a0 = 0.f, a1 = 0.f;
        for (int j = s0; j < s0 + cnt; j++) {
            int sl = es[j];
            a0 += ts[sl * 64 + lane];
            a1 += ts[sl * 64 + 32 + lane];
        }
        float inv = 1.0f / (float)max(cnt, 1);
        out_h[node * 64 + lane]      = fmaf(a0, inv, g_self[node * 64 + lane]);
        out_h[node * 64 + 32 + lane] = fmaf(a1, inv, g_self[node * 64 + 32 + lane]);
    }
}

// ---------------- aggregation 2 + sort-pool fused ----------------
// dyn smem: ts [NPG*64] | hs [NPG*64] | pe [EB] ints | es [EB] bytes
__global__ void aggregate2_pool() {
    extern __shared__ float dyn[];
    float* ts = dyn;
    float* hs = dyn + NPG * HH;
    int*   pe = (int*)(dyn + 2 * NPG * HH);
    unsigned char* es = (unsigned char*)(pe + EB);
    __shared__ int deg[96], offs[96], cur[96];
    __shared__ float key[NPG];
    __shared__ int order[KK];

    int g = blockIdx.x;
    int base = g * NPG;
    int t = threadIdx.x;

    for (int i = t; i < NPG * HH; i += 256)
        ts[i] = g_t[base * HH + i];
    int edges = min(g_gcnt[g], EB);
    for (int i = t; i < edges; i += 256)
        pe[i] = g_ebuck[g * EB + i];
    __syncthreads();

    csort_edges(pe, edges, deg, offs, cur, es, t);

    int wid = t >> 5, lane = t & 31;
    for (int n = wid; n < NPG; n += 8) {
        int node = base + n;
        int s0 = offs[n], cnt = deg[n];
        float a0 = 0.f, a1 = 0.f;
        for (int j = s0; j < s0 + cnt; j++) {
            int sl = es[j];
            a0 += ts[sl * 64 + lane];
            a1 += ts[sl * 64 + 32 + lane];
        }
        float inv = 1.0f / (float)max(cnt, 1);
        hs[n * 64 + lane]      = fmaf(a0, inv, g_self[node * 64 + lane]);
        hs[n * 64 + 32 + lane] = fmaf(a1, inv, g_self[node * 64 + 32 + lane]);
    }
    __syncthreads();

    if (t < NPG) key[t] = hs[t * 64 + 63];
    __syncthreads();
    if (t < NPG) {
        float kv = key[t];
        int rank = 0;
        #pragma unroll 6
        for (int j = 0; j < NPG; j++) {
            float kj = key[j];
            rank += (kj > kv) || (kj == kv && j < t);
        }
        if (rank < KK) order[rank] = t;
    }
    __syncthreads();
    for (int idx = t; idx < PDIM; idx += 256) {
        int r = idx >> 6, f = idx & 63;
        g_p[g * PDIM + idx] = hs[order[r] * 64 + f];
    }
}

// ---------------- MLP head ----------------
#define MLP_GPB 4
#define KCH 128
__global__ void mlp_kernel(const float* __restrict__ Wl1,
                           const float* __restrict__ bl1,
                           const float* __restrict__ Wl2,
                           const float* __restrict__ bl2,
                           float* __restrict__ out) {
    __shared__ float Ws[KCH * 64];          // 32 KB
    __shared__ float Ps[KCH * MLP_GPB];     // 2 KB, [kk][g]
    __shared__ float red[4 * MLP_GPB * 64]; // 4 KB

    int t = threadIdx.x;
    int c = t & 63;
    int q = t >> 6;      // 0..3
    int gbase = blockIdx.x * MLP_GPB;

    float acc[MLP_GPB];
    #pragma unroll
    for (int i = 0; i < MLP_GPB; i++) acc[i] = 0.f;

    for (int k0 = 0; k0 < PDIM; k0 += KCH) {
        for (int idx = t; idx < KCH * 64; idx += 256)
            Ws[idx] = Wl1[(k0 + (idx >> 6)) * 64 + (idx & 63)];
        for (int idx = t; idx < KCH * MLP_GPB; idx += 256) {
            int kk = idx >> 2, gg = idx & 3;
            Ps[kk * MLP_GPB + gg] = g_p[(gbase + gg) * PDIM + k0 + kk];
        }
        __syncthreads();

        int kb = q * (KCH / 4);
        #pragma unroll 8
        for (int kk = 0; kk < KCH / 4; kk++) {
            int k = kb + kk;
            float w = Ws[k * 64 + c];
            float4 pv = *(const float4*)&Ps[k * MLP_GPB];
            acc[0] = fmaf(pv.x, w, acc[0]);
            acc[1] = fmaf(pv.y, w, acc[1]);
            acc[2] = fmaf(pv.z, w, acc[2]);
            acc[3] = fmaf(pv.w, w, acc[3]);
        }
        __syncthreads();
    }

    #pragma unroll
    for (int gg = 0; gg < MLP_GPB; gg++)
        red[(q * MLP_GPB + gg) * 64 + c] = acc[gg];
    __syncthreads();

    {
        int gg = t >> 6;
        float s = red[(0 * MLP_GPB + gg) * 64 + c]
                + red[(1 * MLP_GPB + gg) * 64 + c]
                + red[(2 * MLP_GPB + gg) * 64 + c]
                + red[(3 * MLP_GPB + gg) * 64 + c];
        s += bl1[c];
        __syncthreads();
        red[gg * 64 + c] = s * Wl2[c];
    }
    __syncthreads();

    if (t < MLP_GPB) {
        float dot = bl2[0];
        #pragma unroll 8
        for (int cc = 0; cc < 64; cc++)
            dot += red[t * 64 + cc];
        out[gbase + t] = 1.0f / (1.0f + expf(-dot));
    }
}

// ---------------- launch (single stream — graph-capture safe) ----------------
extern "C" void kernel_launch(void* const* d_in, const int* in_sizes, int n_in,
                              void* d_out, int out_size) {
    const float* x   = (const float*)d_in[0];
    const int*   ei  = (const int*)d_in[1];
    const float* W1l = (const float*)d_in[3];
    const float* W1r = (const float*)d_in[4];
    const float* b1  = (const float*)d_in[5];
    const float* W2l = (const float*)d_in[6];
    const float* W2r = (const float*)d_in[7];
    const float* b2  = (const float*)d_in[8];
    const float* Wl1 = (const float*)d_in[9];
    const float* bl1 = (const float*)d_in[10];
    const float* Wl2 = (const float*)d_in[11];
    const float* bl2 = (const float*)d_in[12];

    float* out_scores = (float*)d_out;              // [512]
    float* out_xtrain = (float*)d_out + G_;         // [46080*64]

    const int* src = ei;
    const int* dst = ei + EE;

    const int smem_g1   = (F_IN * 128 + 32 * F_IN) * 4;   // 57.6 KB
    const int smem_g2   = (HH * 128 + 32 * HH) * 4;       // 40.8 KB
    const int smem_agg1 = NPG * HH * 4 + EB * 4 + EB;     // ~34.6 KB
    const int smem_agg2 = 2 * NPG * HH * 4 + EB * 4 + EB; // ~57.6 KB

    static bool s_init = false;
    if (!s_init) {
        (void)cudaFuncSetAttribute(gemm_dual<F_IN, false>,
                                   cudaFuncAttributeMaxDynamicSharedMemorySize, smem_g1);
        (void)cudaFuncSetAttribute(aggregate2_pool,
                                   cudaFuncAttributeMaxDynamicSharedMemorySize, smem_agg2);
        s_init = true;
    }

    // edge bucketing (replaces 4-kernel CSR build)
    zero512<<<1, 512>>>();
    bucket_kernel<<<EE / 256, 256>>>(src, dst);

    // conv1
    gemm_dual<F_IN, false><<<NN / 128, 256, smem_g1>>>(x, W1l, W1r, b1);
    aggregate1<<<G_, 256, smem_agg1>>>(out_xtrain);

    // conv2 (relu applied on load of x_train)
    gemm_dual<HH, true><<<NN / 128, 256, smem_g2>>>(out_xtrain, W2l, W2r, b2);
    aggregate2_pool<<<G_, 256, smem_agg2>>>();

    // MLP head
    mlp_kernel<<<G_ / MLP_GPB, 256>>>(Wl1, bl1, Wl2, bl2, out_scores);
}

// round 9
// speedup vs baseline: 1.2147x; 1.2147x over previous
#include <cuda_runtime.h>
#include <cuda_bf16.h>
#include <math.h>

#define G_   512
#define NPG  90
#define NN   (G_ * NPG)      // 46080
#define DEG  20
#define EE   (NN * DEG)      // 921600
#define F_IN 90
#define HH   64
#define KK   70
#define PDIM (KK * HH)       // 4480
#define ECAP 2560            // per-graph edge staging capacity (mean 1800, sd ~42)

// ---------------- device scratch (static, no allocations) ----------------
__device__ float g_t[NN * HH];      // X @ Wl  (message features)
__device__ float g_self[NN * HH];   // X @ Wr + b (self features)
__device__ float g_p[G_ * PDIM];    // pooled features
__device__ int   g_cnt[NN];
__device__ int   g_cur[NN];
__device__ int   g_off[NN + 1];
__device__ int   g_eidx[EE];

// ---------------- CSR build ----------------
__global__ void zero_kernel() {
    int i = blockIdx.x * blockDim.x + threadIdx.x;
    if (i < NN) { g_cnt[i] = 0; g_cur[i] = 0; }
}

__global__ void count_kernel(const int* __restrict__ dst) {
    int e = blockIdx.x * blockDim.x + threadIdx.x;
    if (e < EE) {
        int d = dst[e];
        if ((unsigned)d < NN) atomicAdd(&g_cnt[d], 1);
    }
}

// single block, 1024 threads, 45 elems/thread (46080 = 1024*45)
__global__ void scan_kernel() {
    __shared__ int sums[1024];
    int tid = threadIdx.x;
    int base = tid * 45;
    int run = 0;
    #pragma unroll 5
    for (int i = 0; i < 45; i++) run += g_cnt[base + i];
    sums[tid] = run;
    __syncthreads();
    for (int d = 1; d < 1024; d <<= 1) {
        int v = 0;
        if (tid >= d) v = sums[tid - d];
        __syncthreads();
        if (tid >= d) sums[tid] += v;
        __syncthreads();
    }
    int pre = (tid == 0) ? 0 : sums[tid - 1];
    #pragma unroll 5
    for (int i = 0; i < 45; i++) {
        g_off[base + i] = pre;
        pre += g_cnt[base + i];
    }
    if (tid == 1023) g_off[NN] = pre;
}

__global__ void fill_kernel(const int* __restrict__ src,
                            const int* __restrict__ dst) {
    int e = blockIdx.x * blockDim.x + threadIdx.x;
    if (e < EE) {
        int d = dst[e];
        int s = src[e];
        if ((unsigned)d < NN && (unsigned)s < NN) {
            int p = atomicAdd(&g_cur[d], 1);
            g_eidx[g_off[d] + p] = s;
        }
    }
}

// ---------------- fused dual GEMM: T = X@Wl ; S = X@Wr + b ----------------
// blockDim 256; 128 rows per block (4 passes of 32 rows, 4 rowgroups x 8 rows)
template <int K, bool RELU>
__global__ void gemm_dual(const float* __restrict__ X,
                          const float* __restrict__ Wl,
                          const float* __restrict__ Wr,
                          const float* __restrict__ bias) {
    extern __shared__ float smem[];
    float* Ws = smem;               // [K][128]
    float* Xs = smem + K * 128;     // [32][K]

    int t = threadIdx.x;
    int c = t & 63;
    int rg = t >> 6;                // 0..3

    for (int idx = t; idx < K * 128; idx += 256) {
        int k = idx >> 7, cc = idx & 127;
        Ws[idx] = (cc < 64) ? Wl[k * 64 + cc] : Wr[k * 64 + (cc - 64)];
    }
    __syncthreads();

    int rowBase = blockIdx.x * 128;
    float bv = bias[c];

    for (int p = 0; p < 4; p++) {
        int r0 = rowBase + p * 32;
        for (int idx = t; idx < 32 * K; idx += 256) {
            int row = idx / K, k = idx - row * K;
            float v = X[(r0 + row) * K + k];
            Xs[row * K + k] = RELU ? fmaxf(v, 0.f) : v;
        }
        __syncthreads();

        float acc0[8], acc1[8];
        #pragma unroll
        for (int i = 0; i < 8; i++) { acc0[i] = 0.f; acc1[i] = 0.f; }

        const float* xb = Xs + (rg * 8) * K;
        #pragma unroll 2
        for (int k = 0; k < K; k++) {
            float w0 = Ws[k * 128 + c];
            float w1 = Ws[k * 128 + 64 + c];
            #pragma unroll
            for (int i = 0; i < 8; i++) {
                float xv = xb[i * K + k];
                acc0[i] = fmaf(xv, w0, acc0[i]);
                acc1[i] = fmaf(xv, w1, acc1[i]);
            }
        }
        #pragma unroll
        for (int i = 0; i < 8; i++) {
            int row = r0 + rg * 8 + i;
            g_t[row * 64 + c]    = acc0[i];
            g_self[row * 64 + c] = acc1[i] + bv;
        }
        __syncthreads();
    }
}

// ---------------- ILP edge-gather: 4-way unrolled, 8 accumulators ----------------
__device__ __forceinline__ void gather_edges(const float* ts, const int* es,
                                             int s0, int s1, int lane,
                                             float& out0, float& out1) {
    float a0 = 0.f, a1 = 0.f, b0 = 0.f, b1 = 0.f;
    float c0 = 0.f, c1 = 0.f, d0 = 0.f, d1 = 0.f;
    int j = s0;
    for (; j + 3 < s1; j += 4) {
        int sl0 = es[j];
        int sl1 = es[j + 1];
        int sl2 = es[j + 2];
        int sl3 = es[j + 3];
        a0 += ts[sl0 * 64 + lane];      a1 += ts[sl0 * 64 + 32 + lane];
        b0 += ts[sl1 * 64 + lane];      b1 += ts[sl1 * 64 + 32 + lane];
        c0 += ts[sl2 * 64 + lane];      c1 += ts[sl2 * 64 + 32 + lane];
        d0 += ts[sl3 * 64 + lane];      d1 += ts[sl3 * 64 + 32 + lane];
    }
    for (; j < s1; j++) {
        int sl = es[j];
        a0 += ts[sl * 64 + lane];
        a1 += ts[sl * 64 + 32 + lane];
    }
    out0 = (a0 + b0) + (c0 + d0);
    out1 = (a1 + b1) + (c1 + d1);
}

// ---------------- aggregation 1: h1 = mean_csr(t) + self -> x_train ----------------
// dyn smem: ts [NPG*64] floats | es [ECAP] ints
__global__ void aggregate1(float* __restrict__ out_h) {
    extern __shared__ float dyn[];
    float* ts = dyn;                        // 23040 B
    int*   es = (int*)(dyn + NPG * HH);     // 10240 B
    __shared__ int offs[NPG + 1];
    int g = blockIdx.x;
    int base = g * NPG;
    int t = threadIdx.x;

    for (int i = t; i < NPG * HH; i += 256)
        ts[i] = g_t[base * HH + i];
    for (int i = t; i <= NPG; i += 256)
        offs[i] = g_off[base + i];
    __syncthreads();

    int s_begin = offs[0];
    int nedge = offs[NPG] - s_begin;
    int ncap = nedge < ECAP ? nedge : ECAP;
    for (int i = t; i < ncap; i += 256)
        es[i] = g_eidx[s_begin + i] - base;
    __syncthreads();

    int wid = t >> 5, lane = t & 31;
    for (int n = wid; n < NPG; n += 8) {
        int node = base + n;
        int s0 = offs[n] - s_begin, s1 = offs[n + 1] - s_begin;
        if (s1 > ECAP) s1 = ECAP;   // safety (never hit in practice)
        float a0, a1;
        gather_edges(ts, es, s0, s1, lane, a0, a1);
        int cnt = offs[n + 1] - offs[n];
        float inv = 1.0f / (float)max(cnt, 1);
        out_h[node * 64 + lane]      = fmaf(a0, inv, g_self[node * 64 + lane]);
        out_h[node * 64 + 32 + lane] = fmaf(a1, inv, g_self[node * 64 + 32 + lane]);
    }
}

// ---------------- aggregation 2 + sort-pool fused ----------------
// dyn smem: ts [NPG*64] | hs [NPG*64] | es [ECAP] ints
__global__ void aggregate2_pool() {
    extern __shared__ float dyn[];
    float* ts = dyn;
    float* hs = dyn + NPG * HH;
    int*   es = (int*)(dyn + 2 * NPG * HH);
    __shared__ int offs[NPG + 1];
    __shared__ float key[NPG];
    __shared__ int order[KK];

    int g = blockIdx.x;
    int base = g * NPG;
    int t = threadIdx.x;

    for (int i = t; i < NPG * HH; i += 256)
        ts[i] = g_t[base * HH + i];
    for (int i = t; i <= NPG; i += 256)
        offs[i] = g_off[base + i];
    __syncthreads();

    int s_begin = offs[0];
    int nedge = offs[NPG] - s_begin;
    int ncap = nedge < ECAP ? nedge : ECAP;
    for (int i = t; i < ncap; i += 256)
        es[i] = g_eidx[s_begin + i] - base;
    __syncthreads();

    int wid = t >> 5, lane = t & 31;
    for (int n = wid; n < NPG; n += 8) {
        int node = base + n;
        int s0 = offs[n] - s_begin, s1 = offs[n + 1] - s_begin;
        if (s1 > ECAP) s1 = ECAP;
        float a0, a1;
        gather_edges(ts, es, s0, s1, lane, a0, a1);
        int cnt = offs[n + 1] - offs[n];
        float inv = 1.0f / (float)max(cnt, 1);
        hs[n * 64 + lane]      = fmaf(a0, inv, g_self[node * 64 + lane]);
        hs[n * 64 + 32 + lane] = fmaf(a1, inv, g_self[node * 64 + 32 + lane]);
    }
    __syncthreads();

    if (t < NPG) key[t] = hs[t * 64 + 63];
    __syncthreads();
    if (t < NPG) {
        float kv = key[t];
        int rank = 0;
        #pragma unroll 6
        for (int j = 0; j < NPG; j++) {
            float kj = key[j];
            rank += (kj > kv) || (kj == kv && j < t);
        }
        if (rank < KK) order[rank] = t;
    }
    __syncthreads();
    for (int idx = t; idx < PDIM; idx += 256) {
        int r = idx >> 6, f = idx & 63;
        g_p[g * PDIM + idx] = hs[order[r] * 64 + f];
    }
}

// ---------------- MLP head ----------------
#define MLP_GPB 4
#define KCH 128
__global__ void mlp_kernel(const float* __restrict__ Wl1,
                           const float* __restrict__ bl1,
                           const float* __restrict__ Wl2,
                           const float* __restrict__ bl2,
                           float* __restrict__ out) {
    __shared__ float Ws[KCH * 64];          // 32 KB
    __shared__ float Ps[KCH * MLP_GPB];     // 2 KB, [kk][g]
    __shared__ float red[4 * MLP_GPB * 64]; // 4 KB

    int t = threadIdx.x;
    int c = t & 63;
    int q = t >> 6;      // 0..3
    int gbase = blockIdx.x * MLP_GPB;

    float acc[MLP_GPB];
    #pragma unroll
    for (int i = 0; i < MLP_GPB; i++) acc[i] = 0.f;

    for (int k0 = 0; k0 < PDIM; k0 += KCH) {
        for (int idx = t; idx < KCH * 64; idx += 256)
            Ws[idx] = Wl1[(k0 + (idx >> 6)) * 64 + (idx & 63)];
        for (int idx = t; idx < KCH * MLP_GPB; idx += 256) {
            int kk = idx >> 2, gg = idx & 3;
            Ps[kk * MLP_GPB + gg] = g_p[(gbase + gg) * PDIM + k0 + kk];
        }
        __syncthreads();

        int kb = q * (KCH / 4);
        #pragma unroll 8
        for (int kk = 0; kk < KCH / 4; kk++) {
            int k = kb + kk;
            float w = Ws[k * 64 + c];
            float4 pv = *(const float4*)&Ps[k * MLP_GPB];
            acc[0] = fmaf(pv.x, w, acc[0]);
            acc[1] = fmaf(pv.y, w, acc[1]);
            acc[2] = fmaf(pv.z, w, acc[2]);
            acc[3] = fmaf(pv.w, w, acc[3]);
        }
        __syncthreads();
    }

    #pragma unroll
    for (int gg = 0; gg < MLP_GPB; gg++)
        red[(q * MLP_GPB + gg) * 64 + c] = acc[gg];
    __syncthreads();

    {
        int gg = t >> 6;
        float s = red[(0 * MLP_GPB + gg) * 64 + c]
                + red[(1 * MLP_GPB + gg) * 64 + c]
                + red[(2 * MLP_GPB + gg) * 64 + c]
                + red[(3 * MLP_GPB + gg) * 64 + c];
        s += bl1[c];
        __syncthreads();
        red[gg * 64 + c] = s * Wl2[c];
    }
    __syncthreads();

    if (t < MLP_GPB) {
        float dot = bl2[0];
        #pragma unroll 8
        for (int cc = 0; cc < 64; cc++)
            dot += red[t * 64 + cc];
        out[gbase + t] = 1.0f / (1.0f + expf(-dot));
    }
}

// ---------------- launch (single stream — graph-capture safe) ----------------
extern "C" void kernel_launch(void* const* d_in, const int* in_sizes, int n_in,
                              void* d_out, int out_size) {
    const float* x   = (const float*)d_in[0];
    const int*   ei  = (const int*)d_in[1];
    const float* W1l = (const float*)d_in[3];
    const float* W1r = (const float*)d_in[4];
    const float* b1  = (const float*)d_in[5];
    const float* W2l = (const float*)d_in[6];
    const float* W2r = (const float*)d_in[7];
    const float* b2  = (const float*)d_in[8];
    const float* Wl1 = (const float*)d_in[9];
    const float* bl1 = (const float*)d_in[10];
    const float* Wl2 = (const float*)d_in[11];
    const float* bl2 = (const float*)d_in[12];

    float* out_scores = (float*)d_out;              // [512]
    float* out_xtrain = (float*)d_out + G_;         // [46080*64]

    const int* src = ei;
    const int* dst = ei + EE;

    const int smem_g1   = (F_IN * 128 + 32 * F_IN) * 4;   // 57.6 KB
    const int smem_g2   = (HH * 128 + 32 * HH) * 4;       // 40.8 KB
    const int smem_agg1 = NPG * HH * 4 + ECAP * 4;        // 33.3 KB
    const int smem_agg2 = 2 * NPG * HH * 4 + ECAP * 4;    // 56.3 KB

    static bool s_init = false;
    if (!s_init) {
        (void)cudaFuncSetAttribute(gemm_dual<F_IN, false>,
                                   cudaFuncAttributeMaxDynamicSharedMemorySize, smem_g1);
        (void)cudaFuncSetAttribute(aggregate2_pool,
                                   cudaFuncAttributeMaxDynamicSharedMemorySize, smem_agg2);
        s_init = true;
    }

    // CSR build
    zero_kernel<<<(NN + 255) / 256, 256>>>();
    count_kernel<<<EE / 256, 256>>>(dst);
    scan_kernel<<<1, 1024>>>();
    fill_kernel<<<EE / 256, 256>>>(src, dst);

    // conv1
    gemm_dual<F_IN, false><<<NN / 128, 256, smem_g1>>>(x, W1l, W1r, b1);
    aggregate1<<<G_, 256, smem_agg1>>>(out_xtrain);

    // conv2 (relu applied on load of x_train)
    gemm_dual<HH, true><<<NN / 128, 256, smem_g2>>>(out_xtrain, W2l, W2r, b2);
    aggregate2_pool<<<G_, 256, smem_agg2>>>();

    // MLP head
    mlp_kernel<<<G_ / MLP_GPB, 256>>>(Wl1, bl1, Wl2, bl2, out_scores);
}